// round 2
// baseline (speedup 1.0000x reference)
#include <cuda_runtime.h>
#include <math.h>
#include <stdint.h>

// Problem dims (fixed by the dataset)
#define T_TOK 1024
#define HDIM  2048
#define NEXP  16
#define IDIM  1408     // moe_intermediate
#define GU2   2816     // 2*I (routed gate+up rows)
#define SIDIM 2816     // I*S (shared intermediate)
#define SGU2  5632     // 2*I*S
#define TOPK  4

// ---------------- device scratch (static globals; no runtime alloc) ----------------
__device__ int   g_count[NEXP];
__device__ int   g_list[NEXP * T_TOK];                 // packed assignment: t*4 + k
__device__ float g_topw[T_TOK * TOPK];                 // normalized top-k weights
__device__ float g_act_r[(size_t)NEXP * T_TOK * IDIM]; // routed SiLU(g)*u, per expert slot
__device__ float g_ds[(size_t)T_TOK * TOPK * HDIM];    // weighted down output per assignment
__device__ float g_act_s[(size_t)T_TOK * SIDIM];       // shared-expert SiLU(g)*u

// ---------------- router ----------------
__global__ void zero_counts_kernel() {
    if (threadIdx.x < NEXP) g_count[threadIdx.x] = 0;
}

__global__ __launch_bounds__(128) void router_kernel(const float* __restrict__ x,
                                                     const float* __restrict__ gw) {
    const int t = blockIdx.x;
    const int tid = threadIdx.x;          // 128
    const int e = tid & 15;
    const int lane = tid >> 4;            // 0..7
    const float* xr = x + (size_t)t * HDIM;
    const float* wr = gw + (size_t)e * HDIM;
    float p = 0.f;
    for (int h = lane; h < HDIM; h += 8) p += xr[h] * wr[h];
    __shared__ float red[16][8];
    red[e][lane] = p;
    __syncthreads();
    if (tid < 16) {
        float s = 0.f;
        #pragma unroll
        for (int j = 0; j < 8; j++) s += red[tid][j];
        red[tid][0] = s;
    }
    __syncthreads();
    if (tid == 0) {
        float lg[16], pr[16];
        float mx = -1e30f;
        #pragma unroll
        for (int i = 0; i < 16; i++) { lg[i] = red[i][0]; mx = fmaxf(mx, lg[i]); }
        float sum = 0.f;
        #pragma unroll
        for (int i = 0; i < 16; i++) { pr[i] = expf(lg[i] - mx); sum += pr[i]; }
        #pragma unroll
        for (int i = 0; i < 16; i++) pr[i] /= sum;
        int used = 0;
        int   idx[TOPK];
        float wv[TOPK];
        float wsum = 0.f;
        #pragma unroll
        for (int k = 0; k < TOPK; k++) {
            float best = -1.f; int bi = 0;
            #pragma unroll
            for (int i = 0; i < 16; i++)
                if (!((used >> i) & 1) && pr[i] > best) { best = pr[i]; bi = i; }
            used |= (1 << bi);
            idx[k] = bi; wv[k] = best; wsum += best;
        }
        #pragma unroll
        for (int k = 0; k < TOPK; k++) {
            g_topw[t * TOPK + k] = wv[k] / wsum;
            int slot = atomicAdd(&g_count[idx[k]], 1);
            g_list[idx[k] * T_TOK + slot] = t * TOPK + k;
        }
    }
}

// ---------------- tiled GEMM helpers (BM=BN=64, BK=16, 256 threads, 4x4 micro) ----------------

// Routed fused gate/up: per-expert gather GEMM + SiLU*u -> g_act_r
__global__ __launch_bounds__(256) void routed_gu_kernel(const float* __restrict__ x,
                                                        const float* __restrict__ wgu) {
    const int e = blockIdx.z;
    const int cnt = g_count[e];
    const int m0 = blockIdx.x * 64;
    if (m0 >= cnt) return;
    const int n0 = blockIdx.y * 64;

    __shared__ float As[16][64];
    __shared__ float Bg[16][64];
    __shared__ float Bu[16][64];
    __shared__ int toks[64];

    const int tid = threadIdx.x;
    if (tid < 64) {
        int r = m0 + tid;
        toks[tid] = (r < cnt) ? (g_list[e * T_TOK + r] >> 2) : -1;
    }
    __syncthreads();

    const int lm = tid >> 2;
    const int lk = (tid & 3) * 4;
    const int tm = tid >> 4;
    const int tn = tid & 15;

    const int tokA = toks[lm];
    const float* xrow = (tokA >= 0) ? (x + (size_t)tokA * HDIM) : x;  // dummy ptr, masked below
    const bool aval = (tokA >= 0);
    const float* wg_base = wgu + ((size_t)e * GU2 + n0) * HDIM;

    float accg[4][4] = {}, accu[4][4] = {};

    for (int k0 = 0; k0 < HDIM; k0 += 16) {
        float4 av = make_float4(0.f, 0.f, 0.f, 0.f);
        if (aval) av = *(const float4*)(xrow + k0 + lk);
        As[lk + 0][lm] = av.x; As[lk + 1][lm] = av.y;
        As[lk + 2][lm] = av.z; As[lk + 3][lm] = av.w;
        float4 bg = *(const float4*)(wg_base + (size_t)lm * HDIM + k0 + lk);
        float4 bu = *(const float4*)(wg_base + ((size_t)(IDIM + lm)) * HDIM + k0 + lk);
        Bg[lk + 0][lm] = bg.x; Bg[lk + 1][lm] = bg.y;
        Bg[lk + 2][lm] = bg.z; Bg[lk + 3][lm] = bg.w;
        Bu[lk + 0][lm] = bu.x; Bu[lk + 1][lm] = bu.y;
        Bu[lk + 2][lm] = bu.z; Bu[lk + 3][lm] = bu.w;
        __syncthreads();
        #pragma unroll
        for (int kk = 0; kk < 16; ++kk) {
            const float4 a4 = *(const float4*)(&As[kk][tm * 4]);
            const float4 g4 = *(const float4*)(&Bg[kk][tn * 4]);
            const float4 u4 = *(const float4*)(&Bu[kk][tn * 4]);
            const float a[4] = {a4.x, a4.y, a4.z, a4.w};
            const float g[4] = {g4.x, g4.y, g4.z, g4.w};
            const float u[4] = {u4.x, u4.y, u4.z, u4.w};
            #pragma unroll
            for (int i = 0; i < 4; ++i)
                #pragma unroll
                for (int j = 0; j < 4; ++j) {
                    accg[i][j] += a[i] * g[j];
                    accu[i][j] += a[i] * u[j];
                }
        }
        __syncthreads();
    }

    #pragma unroll
    for (int i = 0; i < 4; ++i) {
        int r = m0 + tm * 4 + i;
        if (r >= cnt) continue;
        float* orow = g_act_r + ((size_t)e * T_TOK + r) * IDIM + n0 + tn * 4;
        #pragma unroll
        for (int j = 0; j < 4; ++j) {
            float gv = accg[i][j], uv = accu[i][j];
            orow[j] = (gv / (1.f + expf(-gv))) * uv;
        }
    }
}

// Routed down: per-expert GEMM over act, scaled by topk weight -> g_ds[assign]
__global__ __launch_bounds__(256) void routed_down_kernel(const float* __restrict__ wdown) {
    const int e = blockIdx.z;
    const int cnt = g_count[e];
    const int m0 = blockIdx.x * 64;
    if (m0 >= cnt) return;
    const int n0 = blockIdx.y * 64;   // over HDIM

    __shared__ float As[16][64];
    __shared__ float Bs[16][64];
    __shared__ int asg[64];

    const int tid = threadIdx.x;
    if (tid < 64) {
        int r = m0 + tid;
        asg[tid] = (r < cnt) ? g_list[e * T_TOK + r] : -1;
    }
    __syncthreads();

    const int lm = tid >> 2;
    const int lk = (tid & 3) * 4;
    const int tm = tid >> 4;
    const int tn = tid & 15;

    const bool aval = (m0 + lm) < cnt;
    const float* arow = g_act_r + ((size_t)e * T_TOK + (m0 + lm)) * IDIM;
    const float* brow = wdown + ((size_t)e * HDIM + n0 + lm) * IDIM;

    float acc[4][4] = {};

    for (int k0 = 0; k0 < IDIM; k0 += 16) {
        float4 av = make_float4(0.f, 0.f, 0.f, 0.f);
        if (aval) av = *(const float4*)(arow + k0 + lk);
        As[lk + 0][lm] = av.x; As[lk + 1][lm] = av.y;
        As[lk + 2][lm] = av.z; As[lk + 3][lm] = av.w;
        float4 bv = *(const float4*)(brow + k0 + lk);
        Bs[lk + 0][lm] = bv.x; Bs[lk + 1][lm] = bv.y;
        Bs[lk + 2][lm] = bv.z; Bs[lk + 3][lm] = bv.w;
        __syncthreads();
        #pragma unroll
        for (int kk = 0; kk < 16; ++kk) {
            const float4 a4 = *(const float4*)(&As[kk][tm * 4]);
            const float4 b4 = *(const float4*)(&Bs[kk][tn * 4]);
            const float a[4] = {a4.x, a4.y, a4.z, a4.w};
            const float b[4] = {b4.x, b4.y, b4.z, b4.w};
            #pragma unroll
            for (int i = 0; i < 4; ++i)
                #pragma unroll
                for (int j = 0; j < 4; ++j) acc[i][j] += a[i] * b[j];
        }
        __syncthreads();
    }

    #pragma unroll
    for (int i = 0; i < 4; ++i) {
        int r = m0 + tm * 4 + i;
        if (r >= cnt) continue;
        int a = asg[tm * 4 + i];
        float w = g_topw[a];
        float* orow = g_ds + (size_t)a * HDIM + n0 + tn * 4;
        #pragma unroll
        for (int j = 0; j < 4; ++j) orow[j] = acc[i][j] * w;
    }
}

// Shared expert fused gate/up -> g_act_s
__global__ __launch_bounds__(256) void shared_gu_kernel(const float* __restrict__ x,
                                                        const float* __restrict__ sgu) {
    const int m0 = blockIdx.x * 64;
    const int n0 = blockIdx.y * 64;   // over SIDIM

    __shared__ float As[16][64];
    __shared__ float Bg[16][64];
    __shared__ float Bu[16][64];

    const int tid = threadIdx.x;
    const int lm = tid >> 2;
    const int lk = (tid & 3) * 4;
    const int tm = tid >> 4;
    const int tn = tid & 15;

    const float* xrow = x + (size_t)(m0 + lm) * HDIM;
    const float* wg_base = sgu + (size_t)(n0) * HDIM;

    float accg[4][4] = {}, accu[4][4] = {};

    for (int k0 = 0; k0 < HDIM; k0 += 16) {
        float4 av = *(const float4*)(xrow + k0 + lk);
        As[lk + 0][lm] = av.x; As[lk + 1][lm] = av.y;
        As[lk + 2][lm] = av.z; As[lk + 3][lm] = av.w;
        float4 bg = *(const float4*)(wg_base + (size_t)lm * HDIM + k0 + lk);
        float4 bu = *(const float4*)(wg_base + ((size_t)(SIDIM + lm)) * HDIM + k0 + lk);
        Bg[lk + 0][lm] = bg.x; Bg[lk + 1][lm] = bg.y;
        Bg[lk + 2][lm] = bg.z; Bg[lk + 3][lm] = bg.w;
        Bu[lk + 0][lm] = bu.x; Bu[lk + 1][lm] = bu.y;
        Bu[lk + 2][lm] = bu.z; Bu[lk + 3][lm] = bu.w;
        __syncthreads();
        #pragma unroll
        for (int kk = 0; kk < 16; ++kk) {
            const float4 a4 = *(const float4*)(&As[kk][tm * 4]);
            const float4 g4 = *(const float4*)(&Bg[kk][tn * 4]);
            const float4 u4 = *(const float4*)(&Bu[kk][tn * 4]);
            const float a[4] = {a4.x, a4.y, a4.z, a4.w};
            const float g[4] = {g4.x, g4.y, g4.z, g4.w};
            const float u[4] = {u4.x, u4.y, u4.z, u4.w};
            #pragma unroll
            for (int i = 0; i < 4; ++i)
                #pragma unroll
                for (int j = 0; j < 4; ++j) {
                    accg[i][j] += a[i] * g[j];
                    accu[i][j] += a[i] * u[j];
                }
        }
        __syncthreads();
    }

    #pragma unroll
    for (int i = 0; i < 4; ++i) {
        int r = m0 + tm * 4 + i;
        float* orow = g_act_s + (size_t)r * SIDIM + n0 + tn * 4;
        #pragma unroll
        for (int j = 0; j < 4; ++j) {
            float gv = accg[i][j], uv = accu[i][j];
            orow[j] = (gv / (1.f + expf(-gv))) * uv;
        }
    }
}

// Shared expert down -> writes d_out (base value, combine adds routed)
__global__ __launch_bounds__(256) void shared_down_kernel(const float* __restrict__ sdown,
                                                          float* __restrict__ out) {
    const int m0 = blockIdx.x * 64;
    const int n0 = blockIdx.y * 64;   // over HDIM

    __shared__ float As[16][64];
    __shared__ float Bs[16][64];

    const int tid = threadIdx.x;
    const int lm = tid >> 2;
    const int lk = (tid & 3) * 4;
    const int tm = tid >> 4;
    const int tn = tid & 15;

    const float* arow = g_act_s + (size_t)(m0 + lm) * SIDIM;
    const float* brow = sdown + (size_t)(n0 + lm) * SIDIM;

    float acc[4][4] = {};

    for (int k0 = 0; k0 < SIDIM; k0 += 16) {
        float4 av = *(const float4*)(arow + k0 + lk);
        As[lk + 0][lm] = av.x; As[lk + 1][lm] = av.y;
        As[lk + 2][lm] = av.z; As[lk + 3][lm] = av.w;
        float4 bv = *(const float4*)(brow + k0 + lk);
        Bs[lk + 0][lm] = bv.x; Bs[lk + 1][lm] = bv.y;
        Bs[lk + 2][lm] = bv.z; Bs[lk + 3][lm] = bv.w;
        __syncthreads();
        #pragma unroll
        for (int kk = 0; kk < 16; ++kk) {
            const float4 a4 = *(const float4*)(&As[kk][tm * 4]);
            const float4 b4 = *(const float4*)(&Bs[kk][tn * 4]);
            const float a[4] = {a4.x, a4.y, a4.z, a4.w};
            const float b[4] = {b4.x, b4.y, b4.z, b4.w};
            #pragma unroll
            for (int i = 0; i < 4; ++i)
                #pragma unroll
                for (int j = 0; j < 4; ++j) acc[i][j] += a[i] * b[j];
        }
        __syncthreads();
    }

    #pragma unroll
    for (int i = 0; i < 4; ++i) {
        int r = m0 + tm * 4 + i;
        float* orow = out + (size_t)r * HDIM + n0 + tn * 4;
        #pragma unroll
        for (int j = 0; j < 4; ++j) orow[j] = acc[i][j];
    }
}

// out[t,h] += sum_k ds[(t*4+k), h]
__global__ __launch_bounds__(256) void combine_kernel(float* __restrict__ out) {
    int idx = blockIdx.x * blockDim.x + threadIdx.x;
    if (idx >= T_TOK * HDIM) return;
    int t = idx >> 11;          // / HDIM
    int h = idx & (HDIM - 1);
    float s = out[idx];
    #pragma unroll
    for (int k = 0; k < TOPK; ++k)
        s += g_ds[((size_t)(t * TOPK + k)) * HDIM + h];
    out[idx] = s;
}

// ---------------- launch ----------------
extern "C" void kernel_launch(void* const* d_in, const int* in_sizes, int n_in,
                              void* d_out, int out_size) {
    const float* x     = (const float*)d_in[0];   // [1024, 2048]
    const float* gw    = (const float*)d_in[1];   // [16, 2048]
    const float* wgu   = (const float*)d_in[2];   // [16, 2816, 2048]
    const float* wdown = (const float*)d_in[3];   // [16, 2048, 1408]
    const float* sgu   = (const float*)d_in[4];   // [5632, 2048]
    const float* sdown = (const float*)d_in[5];   // [2048, 2816]
    float* out = (float*)d_out;                   // [1024, 2048]

    zero_counts_kernel<<<1, 32>>>();
    router_kernel<<<T_TOK, 128>>>(x, gw);

    {
        dim3 grid(T_TOK / 64, IDIM / 64, NEXP);
        routed_gu_kernel<<<grid, 256>>>(x, wgu);
    }
    {
        dim3 grid(T_TOK / 64, HDIM / 64, NEXP);
        routed_down_kernel<<<grid, 256>>>(wdown);
    }
    {
        dim3 grid(T_TOK / 64, SIDIM / 64);
        shared_gu_kernel<<<grid, 256>>>(x, sgu);
    }
    {
        dim3 grid(T_TOK / 64, HDIM / 64);
        shared_down_kernel<<<grid, 256>>>(sdown, out);
    }
    combine_kernel<<<(T_TOK * HDIM + 255) / 256, 256>>>(out);
}

// round 3
// speedup vs baseline: 1.5094x; 1.5094x over previous
#include <cuda_runtime.h>
#include <math.h>
#include <stdint.h>

// Problem dims (fixed by the dataset)
#define T_TOK 1024
#define HDIM  2048
#define NEXP  16
#define IDIM  1408     // moe_intermediate
#define GU2   2816     // 2*I (routed gate+up rows)
#define SIDIM 2816     // I*S (shared intermediate)
#define TOPK  4

// ---------------- device scratch (static globals; no runtime alloc) ----------------
__device__ int   g_count[NEXP];
__device__ int   g_list[NEXP * T_TOK];                 // packed assignment: t*4 + k
__device__ float g_topw[T_TOK * TOPK];                 // normalized top-k weights
__device__ float g_act_r[(size_t)NEXP * T_TOK * IDIM]; // routed SiLU(g)*u, per expert slot
__device__ float g_ds[(size_t)T_TOK * TOPK * HDIM];    // weighted down output per assignment
__device__ float g_act_s[(size_t)T_TOK * SIDIM];       // shared-expert SiLU(g)*u

// ---------------- helpers ----------------
__device__ __forceinline__ unsigned f2tf(float x) {
    unsigned r;
    asm("cvt.rna.tf32.f32 %0, %1;" : "=r"(r) : "f"(x));
    return r;
}

__device__ __forceinline__ void mma8(float* c, const uint4& a, const uint2& b) {
    asm volatile(
        "mma.sync.aligned.m16n8k8.row.col.f32.tf32.tf32.f32 "
        "{%0,%1,%2,%3}, {%4,%5,%6,%7}, {%8,%9}, {%0,%1,%2,%3};\n"
        : "+f"(c[0]), "+f"(c[1]), "+f"(c[2]), "+f"(c[3])
        : "r"(a.x), "r"(a.y), "r"(a.z), "r"(a.w), "r"(b.x), "r"(b.y));
}

// fragment-order SMEM offsets (units of unsigned)
// A tile 128x32: a_frag[ks(4)][mt(8)][lane(32)][reg(4)]
__device__ __forceinline__ int a_off(int m, int k) {
    int mt = m >> 4, r = m & 15, ks = k >> 3, kc = k & 7;
    int lane = ((r & 7) << 2) | (kc & 3);
    int reg = (r >> 3) | ((kc >> 2) << 1);
    return (((((ks << 3) + mt) << 5) + lane) << 2) + reg;
}
// B tile 64x32: b_frag[ks(4)][nt(8)][lane(32)][reg(2)]
__device__ __forceinline__ int b_off(int n, int k) {
    int nt = n >> 3, g = n & 7, ks = k >> 3, kc = k & 7;
    int lane = (g << 2) | (kc & 3);
    int reg = kc >> 2;
    return (((((ks << 3) + nt) << 5) + lane) << 1) + reg;
}

__device__ __forceinline__ float silu(float g) {
    return g / (1.f + __expf(-g));
}

// ---------------- router ----------------
__global__ void zero_counts_kernel() {
    if (threadIdx.x < NEXP) g_count[threadIdx.x] = 0;
}

__global__ __launch_bounds__(128) void router_kernel(const float* __restrict__ x,
                                                     const float* __restrict__ gw) {
    const int t = blockIdx.x;
    const int tid = threadIdx.x;
    const int e = tid & 15;
    const int lane = tid >> 4;
    const float* xr = x + (size_t)t * HDIM;
    const float* wr = gw + (size_t)e * HDIM;
    float p = 0.f;
    for (int h = lane; h < HDIM; h += 8) p += xr[h] * wr[h];
    __shared__ float red[16][8];
    red[e][lane] = p;
    __syncthreads();
    if (tid < 16) {
        float s = 0.f;
        #pragma unroll
        for (int j = 0; j < 8; j++) s += red[tid][j];
        red[tid][0] = s;
    }
    __syncthreads();
    if (tid == 0) {
        float lg[16], pr[16];
        float mx = -1e30f;
        #pragma unroll
        for (int i = 0; i < 16; i++) { lg[i] = red[i][0]; mx = fmaxf(mx, lg[i]); }
        float sum = 0.f;
        #pragma unroll
        for (int i = 0; i < 16; i++) { pr[i] = expf(lg[i] - mx); sum += pr[i]; }
        #pragma unroll
        for (int i = 0; i < 16; i++) pr[i] /= sum;
        int used = 0;
        int   idx[TOPK];
        float wv[TOPK];
        float wsum = 0.f;
        #pragma unroll
        for (int k = 0; k < TOPK; k++) {
            float best = -1.f; int bi = 0;
            #pragma unroll
            for (int i = 0; i < 16; i++)
                if (!((used >> i) & 1) && pr[i] > best) { best = pr[i]; bi = i; }
            used |= (1 << bi);
            idx[k] = bi; wv[k] = best; wsum += best;
        }
        #pragma unroll
        for (int k = 0; k < TOPK; k++) {
            g_topw[t * TOPK + k] = wv[k] / wsum;
            int slot = atomicAdd(&g_count[idx[k]], 1);
            g_list[idx[k] * T_TOK + slot] = t * TOPK + k;
        }
    }
}

// =====================================================================
// GU-style kernels: C = A[128,K] x {Bg,Bu}[64,K]^T, epilogue SiLU(g)*u
// =====================================================================

__global__ __launch_bounds__(256) void routed_gu_kernel(const float* __restrict__ x,
                                                        const float* __restrict__ wgu) {
    const int e = blockIdx.z;
    const int cnt = g_count[e];
    const int m0 = blockIdx.x * 128;
    if (m0 >= cnt) return;
    const int n0 = blockIdx.y * 64;

    __shared__ unsigned As[4096];
    __shared__ unsigned Bg[2048];
    __shared__ unsigned Bu[2048];
    __shared__ int toks[128];

    const int tid = threadIdx.x;
    if (tid < 128) {
        int r = m0 + tid;
        toks[tid] = (r < cnt) ? (g_list[e * T_TOK + r] >> 2) : -1;
    }
    __syncthreads();

    const int arow = tid >> 1, ak0 = (tid & 1) * 16;
    const int tokA = toks[arow];
    const float* aptr = x + (size_t)(tokA >= 0 ? tokA : 0) * HDIM + ak0;
    const int brow = tid >> 2, bk0 = (tid & 3) * 8;
    const float* bgp = wgu + ((size_t)e * GU2 + n0 + brow) * HDIM + bk0;
    const float* bup = bgp + (size_t)IDIM * HDIM;

    const int lane = tid & 31, wid = tid >> 5, wm = wid & 3, wn = wid >> 2;

    float accg[8][4], accu[8][4];
    #pragma unroll
    for (int i = 0; i < 8; i++)
        #pragma unroll
        for (int j = 0; j < 4; j++) { accg[i][j] = 0.f; accu[i][j] = 0.f; }

    for (int k0 = 0; k0 < HDIM; k0 += 32) {
        float4 av[4];
        #pragma unroll
        for (int q = 0; q < 4; q++)
            av[q] = (tokA >= 0) ? *(const float4*)(aptr + k0 + q * 4)
                                : make_float4(0.f, 0.f, 0.f, 0.f);
        float4 bgv[2], buv[2];
        #pragma unroll
        for (int q = 0; q < 2; q++) {
            bgv[q] = *(const float4*)(bgp + k0 + q * 4);
            buv[q] = *(const float4*)(bup + k0 + q * 4);
        }
        __syncthreads();
        #pragma unroll
        for (int q = 0; q < 4; q++) {
            const float vv[4] = {av[q].x, av[q].y, av[q].z, av[q].w};
            #pragma unroll
            for (int c = 0; c < 4; c++) As[a_off(arow, ak0 + q * 4 + c)] = f2tf(vv[c]);
        }
        #pragma unroll
        for (int q = 0; q < 2; q++) {
            const float vg[4] = {bgv[q].x, bgv[q].y, bgv[q].z, bgv[q].w};
            const float vu[4] = {buv[q].x, buv[q].y, buv[q].z, buv[q].w};
            #pragma unroll
            for (int c = 0; c < 4; c++) {
                int off = b_off(brow, bk0 + q * 4 + c);
                Bg[off] = f2tf(vg[c]);
                Bu[off] = f2tf(vu[c]);
            }
        }
        __syncthreads();
        #pragma unroll
        for (int ks = 0; ks < 4; ks++) {
            uint4 a[2];
            uint2 fg[4], fu[4];
            #pragma unroll
            for (int mi = 0; mi < 2; mi++)
                a[mi] = *(const uint4*)&As[(((((ks << 3) + wm * 2 + mi) << 5) + lane) << 2)];
            #pragma unroll
            for (int ni = 0; ni < 4; ni++) {
                int boff = ((((ks << 3) + (wn << 2) + ni) << 5) + lane) << 1;
                fg[ni] = *(const uint2*)&Bg[boff];
                fu[ni] = *(const uint2*)&Bu[boff];
            }
            #pragma unroll
            for (int mi = 0; mi < 2; mi++)
                #pragma unroll
                for (int ni = 0; ni < 4; ni++) {
                    mma8(accg[mi * 4 + ni], a[mi], fg[ni]);
                    mma8(accu[mi * 4 + ni], a[mi], fu[ni]);
                }
        }
        __syncthreads();
    }

    const int g = lane >> 2, tig = lane & 3;
    #pragma unroll
    for (int mi = 0; mi < 2; mi++)
        #pragma unroll
        for (int ni = 0; ni < 4; ni++) {
            const float* cg = accg[mi * 4 + ni];
            const float* cu = accu[mi * 4 + ni];
            int col = n0 + wn * 32 + ni * 8 + tig * 2;
            int r0 = m0 + wm * 32 + mi * 16 + g;
            if (r0 < cnt) {
                float* o = g_act_r + ((size_t)e * T_TOK + r0) * IDIM + col;
                *(float2*)o = make_float2(silu(cg[0]) * cu[0], silu(cg[1]) * cu[1]);
            }
            int r1 = r0 + 8;
            if (r1 < cnt) {
                float* o = g_act_r + ((size_t)e * T_TOK + r1) * IDIM + col;
                *(float2*)o = make_float2(silu(cg[2]) * cu[2], silu(cg[3]) * cu[3]);
            }
        }
}

__global__ __launch_bounds__(256) void shared_gu_kernel(const float* __restrict__ x,
                                                        const float* __restrict__ sgu) {
    const int m0 = blockIdx.x * 128;
    const int n0 = blockIdx.y * 64;   // over SIDIM

    __shared__ unsigned As[4096];
    __shared__ unsigned Bg[2048];
    __shared__ unsigned Bu[2048];

    const int tid = threadIdx.x;
    const int arow = tid >> 1, ak0 = (tid & 1) * 16;
    const float* aptr = x + (size_t)(m0 + arow) * HDIM + ak0;
    const int brow = tid >> 2, bk0 = (tid & 3) * 8;
    const float* bgp = sgu + (size_t)(n0 + brow) * HDIM + bk0;
    const float* bup = bgp + (size_t)SIDIM * HDIM;

    const int lane = tid & 31, wid = tid >> 5, wm = wid & 3, wn = wid >> 2;

    float accg[8][4], accu[8][4];
    #pragma unroll
    for (int i = 0; i < 8; i++)
        #pragma unroll
        for (int j = 0; j < 4; j++) { accg[i][j] = 0.f; accu[i][j] = 0.f; }

    for (int k0 = 0; k0 < HDIM; k0 += 32) {
        float4 av[4];
        #pragma unroll
        for (int q = 0; q < 4; q++) av[q] = *(const float4*)(aptr + k0 + q * 4);
        float4 bgv[2], buv[2];
        #pragma unroll
        for (int q = 0; q < 2; q++) {
            bgv[q] = *(const float4*)(bgp + k0 + q * 4);
            buv[q] = *(const float4*)(bup + k0 + q * 4);
        }
        __syncthreads();
        #pragma unroll
        for (int q = 0; q < 4; q++) {
            const float vv[4] = {av[q].x, av[q].y, av[q].z, av[q].w};
            #pragma unroll
            for (int c = 0; c < 4; c++) As[a_off(arow, ak0 + q * 4 + c)] = f2tf(vv[c]);
        }
        #pragma unroll
        for (int q = 0; q < 2; q++) {
            const float vg[4] = {bgv[q].x, bgv[q].y, bgv[q].z, bgv[q].w};
            const float vu[4] = {buv[q].x, buv[q].y, buv[q].z, buv[q].w};
            #pragma unroll
            for (int c = 0; c < 4; c++) {
                int off = b_off(brow, bk0 + q * 4 + c);
                Bg[off] = f2tf(vg[c]);
                Bu[off] = f2tf(vu[c]);
            }
        }
        __syncthreads();
        #pragma unroll
        for (int ks = 0; ks < 4; ks++) {
            uint4 a[2];
            uint2 fg[4], fu[4];
            #pragma unroll
            for (int mi = 0; mi < 2; mi++)
                a[mi] = *(const uint4*)&As[(((((ks << 3) + wm * 2 + mi) << 5) + lane) << 2)];
            #pragma unroll
            for (int ni = 0; ni < 4; ni++) {
                int boff = ((((ks << 3) + (wn << 2) + ni) << 5) + lane) << 1;
                fg[ni] = *(const uint2*)&Bg[boff];
                fu[ni] = *(const uint2*)&Bu[boff];
            }
            #pragma unroll
            for (int mi = 0; mi < 2; mi++)
                #pragma unroll
                for (int ni = 0; ni < 4; ni++) {
                    mma8(accg[mi * 4 + ni], a[mi], fg[ni]);
                    mma8(accu[mi * 4 + ni], a[mi], fu[ni]);
                }
        }
        __syncthreads();
    }

    const int g = lane >> 2, tig = lane & 3;
    #pragma unroll
    for (int mi = 0; mi < 2; mi++)
        #pragma unroll
        for (int ni = 0; ni < 4; ni++) {
            const float* cg = accg[mi * 4 + ni];
            const float* cu = accu[mi * 4 + ni];
            int col = n0 + wn * 32 + ni * 8 + tig * 2;
            int r0 = m0 + wm * 32 + mi * 16 + g;
            float* o0 = g_act_s + (size_t)r0 * SIDIM + col;
            *(float2*)o0 = make_float2(silu(cg[0]) * cu[0], silu(cg[1]) * cu[1]);
            float* o1 = g_act_s + (size_t)(r0 + 8) * SIDIM + col;
            *(float2*)o1 = make_float2(silu(cg[2]) * cu[2], silu(cg[3]) * cu[3]);
        }
}

// =====================================================================
// Down-style kernels: C = A[128,K] x B[64,K]^T
// =====================================================================

__global__ __launch_bounds__(256) void routed_down_kernel(const float* __restrict__ wdown) {
    const int e = blockIdx.z;
    const int cnt = g_count[e];
    const int m0 = blockIdx.x * 128;
    if (m0 >= cnt) return;
    const int n0 = blockIdx.y * 64;   // over HDIM

    __shared__ unsigned As[4096];
    __shared__ unsigned Bs[2048];
    __shared__ int asg[128];

    const int tid = threadIdx.x;
    if (tid < 128) {
        int r = m0 + tid;
        asg[tid] = (r < cnt) ? g_list[e * T_TOK + r] : -1;
    }
    __syncthreads();

    const int arow = tid >> 1, ak0 = (tid & 1) * 16;
    const bool aval = (m0 + arow) < cnt;
    const float* aptr = g_act_r + ((size_t)e * T_TOK + m0 + arow) * IDIM + ak0;
    const int brow = tid >> 2, bk0 = (tid & 3) * 8;
    const float* bp = wdown + ((size_t)e * HDIM + n0 + brow) * IDIM + bk0;

    const int lane = tid & 31, wid = tid >> 5, wm = wid & 3, wn = wid >> 2;

    float acc[8][4];
    #pragma unroll
    for (int i = 0; i < 8; i++)
        #pragma unroll
        for (int j = 0; j < 4; j++) acc[i][j] = 0.f;

    for (int k0 = 0; k0 < IDIM; k0 += 32) {
        float4 av[4];
        #pragma unroll
        for (int q = 0; q < 4; q++)
            av[q] = aval ? *(const float4*)(aptr + k0 + q * 4)
                         : make_float4(0.f, 0.f, 0.f, 0.f);
        float4 bv[2];
        #pragma unroll
        for (int q = 0; q < 2; q++) bv[q] = *(const float4*)(bp + k0 + q * 4);
        __syncthreads();
        #pragma unroll
        for (int q = 0; q < 4; q++) {
            const float vv[4] = {av[q].x, av[q].y, av[q].z, av[q].w};
            #pragma unroll
            for (int c = 0; c < 4; c++) As[a_off(arow, ak0 + q * 4 + c)] = f2tf(vv[c]);
        }
        #pragma unroll
        for (int q = 0; q < 2; q++) {
            const float vb[4] = {bv[q].x, bv[q].y, bv[q].z, bv[q].w};
            #pragma unroll
            for (int c = 0; c < 4; c++) Bs[b_off(brow, bk0 + q * 4 + c)] = f2tf(vb[c]);
        }
        __syncthreads();
        #pragma unroll
        for (int ks = 0; ks < 4; ks++) {
            uint4 a[2];
            uint2 fb[4];
            #pragma unroll
            for (int mi = 0; mi < 2; mi++)
                a[mi] = *(const uint4*)&As[(((((ks << 3) + wm * 2 + mi) << 5) + lane) << 2)];
            #pragma unroll
            for (int ni = 0; ni < 4; ni++)
                fb[ni] = *(const uint2*)&Bs[(((((ks << 3) + (wn << 2) + ni) << 5) + lane) << 1)];
            #pragma unroll
            for (int mi = 0; mi < 2; mi++)
                #pragma unroll
                for (int ni = 0; ni < 4; ni++)
                    mma8(acc[mi * 4 + ni], a[mi], fb[ni]);
        }
        __syncthreads();
    }

    const int g = lane >> 2, tig = lane & 3;
    #pragma unroll
    for (int mi = 0; mi < 2; mi++)
        #pragma unroll
        for (int ni = 0; ni < 4; ni++) {
            const float* c = acc[mi * 4 + ni];
            int col = n0 + wn * 32 + ni * 8 + tig * 2;
            int r0 = m0 + wm * 32 + mi * 16 + g;
            if (r0 < cnt) {
                int a = asg[r0 - m0];
                float w = g_topw[a];
                float* o = g_ds + (size_t)a * HDIM + col;
                *(float2*)o = make_float2(c[0] * w, c[1] * w);
            }
            int r1 = r0 + 8;
            if (r1 < cnt) {
                int a = asg[r1 - m0];
                float w = g_topw[a];
                float* o = g_ds + (size_t)a * HDIM + col;
                *(float2*)o = make_float2(c[2] * w, c[3] * w);
            }
        }
}

// shared down + combine of routed outputs -> d_out
__global__ __launch_bounds__(256) void shared_down_kernel(const float* __restrict__ sdown,
                                                          float* __restrict__ out) {
    const int m0 = blockIdx.x * 128;
    const int n0 = blockIdx.y * 64;   // over HDIM

    __shared__ unsigned As[4096];
    __shared__ unsigned Bs[2048];

    const int tid = threadIdx.x;
    const int arow = tid >> 1, ak0 = (tid & 1) * 16;
    const float* aptr = g_act_s + (size_t)(m0 + arow) * SIDIM + ak0;
    const int brow = tid >> 2, bk0 = (tid & 3) * 8;
    const float* bp = sdown + (size_t)(n0 + brow) * SIDIM + bk0;

    const int lane = tid & 31, wid = tid >> 5, wm = wid & 3, wn = wid >> 2;

    float acc[8][4];
    #pragma unroll
    for (int i = 0; i < 8; i++)
        #pragma unroll
        for (int j = 0; j < 4; j++) acc[i][j] = 0.f;

    for (int k0 = 0; k0 < SIDIM; k0 += 32) {
        float4 av[4];
        #pragma unroll
        for (int q = 0; q < 4; q++) av[q] = *(const float4*)(aptr + k0 + q * 4);
        float4 bv[2];
        #pragma unroll
        for (int q = 0; q < 2; q++) bv[q] = *(const float4*)(bp + k0 + q * 4);
        __syncthreads();
        #pragma unroll
        for (int q = 0; q < 4; q++) {
            const float vv[4] = {av[q].x, av[q].y, av[q].z, av[q].w};
            #pragma unroll
            for (int c = 0; c < 4; c++) As[a_off(arow, ak0 + q * 4 + c)] = f2tf(vv[c]);
        }
        #pragma unroll
        for (int q = 0; q < 2; q++) {
            const float vb[4] = {bv[q].x, bv[q].y, bv[q].z, bv[q].w};
            #pragma unroll
            for (int c = 0; c < 4; c++) Bs[b_off(brow, bk0 + q * 4 + c)] = f2tf(vb[c]);
        }
        __syncthreads();
        #pragma unroll
        for (int ks = 0; ks < 4; ks++) {
            uint4 a[2];
            uint2 fb[4];
            #pragma unroll
            for (int mi = 0; mi < 2; mi++)
                a[mi] = *(const uint4*)&As[(((((ks << 3) + wm * 2 + mi) << 5) + lane) << 2)];
            #pragma unroll
            for (int ni = 0; ni < 4; ni++)
                fb[ni] = *(const uint2*)&Bs[(((((ks << 3) + (wn << 2) + ni) << 5) + lane) << 1)];
            #pragma unroll
            for (int mi = 0; mi < 2; mi++)
                #pragma unroll
                for (int ni = 0; ni < 4; ni++)
                    mma8(acc[mi * 4 + ni], a[mi], fb[ni]);
        }
        __syncthreads();
    }

    const int g = lane >> 2, tig = lane & 3;
    #pragma unroll
    for (int mi = 0; mi < 2; mi++)
        #pragma unroll
        for (int ni = 0; ni < 4; ni++) {
            const float* c = acc[mi * 4 + ni];
            int col = n0 + wn * 32 + ni * 8 + tig * 2;
            int r0 = m0 + wm * 32 + mi * 16 + g;
            #pragma unroll
            for (int half = 0; half < 2; half++) {
                int r = r0 + half * 8;
                float s0 = c[half * 2 + 0];
                float s1 = c[half * 2 + 1];
                #pragma unroll
                for (int kk = 0; kk < TOPK; kk++) {
                    float2 d = *(const float2*)(g_ds + (size_t)(r * TOPK + kk) * HDIM + col);
                    s0 += d.x;
                    s1 += d.y;
                }
                *(float2*)(out + (size_t)r * HDIM + col) = make_float2(s0, s1);
            }
        }
}

// ---------------- launch ----------------
extern "C" void kernel_launch(void* const* d_in, const int* in_sizes, int n_in,
                              void* d_out, int out_size) {
    const float* x     = (const float*)d_in[0];   // [1024, 2048]
    const float* gw    = (const float*)d_in[1];   // [16, 2048]
    const float* wgu   = (const float*)d_in[2];   // [16, 2816, 2048]
    const float* wdown = (const float*)d_in[3];   // [16, 2048, 1408]
    const float* sgu   = (const float*)d_in[4];   // [5632, 2048]
    const float* sdown = (const float*)d_in[5];   // [2048, 2816]
    float* out = (float*)d_out;                   // [1024, 2048]

    zero_counts_kernel<<<1, 32>>>();
    router_kernel<<<T_TOK, 128>>>(x, gw);

    {
        dim3 grid(T_TOK / 128, IDIM / 64, NEXP);
        routed_gu_kernel<<<grid, 256>>>(x, wgu);
    }
    {
        dim3 grid(T_TOK / 128, HDIM / 64, NEXP);
        routed_down_kernel<<<grid, 256>>>(wdown);
    }
    {
        dim3 grid(T_TOK / 128, SIDIM / 64);
        shared_gu_kernel<<<grid, 256>>>(x, sgu);
    }
    {
        dim3 grid(T_TOK / 128, HDIM / 64);
        shared_down_kernel<<<grid, 256>>>(sdown, out);
    }
}

// round 9
// speedup vs baseline: 3.2839x; 2.1756x over previous
#include <cuda_runtime.h>
#include <math.h>
#include <stdint.h>

#define T_TOK 1024
#define HDIM  2048
#define NEXP  16
#define IDIM  1408
#define GU2   2816
#define SIDIM 2816
#define SGU2  5632
#define TOPK  4

#define BM 128
#define BN 128
#define BK 32
#define NTHR 256

// ---------------- device scratch ----------------
__device__ int   g_count[NEXP];
__device__ int   g_list[NEXP * T_TOK];                  // assignment: t*4+k
__device__ float g_topw[T_TOK * TOPK];
__device__ float g_xr[(size_t)T_TOK * HDIM];            // rna+comp activations
__device__ float g_gu[(size_t)NEXP * T_TOK * GU2];      // routed gate/up raw gemm out
__device__ float g_act_r[(size_t)NEXP * T_TOK * IDIM];  // routed act (rna+comp)
__device__ float g_gus[(size_t)T_TOK * SGU2];           // shared gate/up raw gemm out
__device__ float g_act_s[(size_t)T_TOK * SIDIM];        // shared act (rna+comp)
__device__ float g_ds[(size_t)T_TOK * TOPK * HDIM];     // weighted routed down

// ---------------- helpers ----------------
__device__ __forceinline__ uint32_t smem_u32(const void* p) {
    uint32_t a;
    asm("{ .reg .u64 t; cvta.to.shared.u64 t, %1; cvt.u32.u64 %0, t; }" : "=r"(a) : "l"(p));
    return a;
}
__device__ __forceinline__ void cpa16(uint32_t dst, const void* src) {
    asm volatile("cp.async.cg.shared.global [%0], [%1], 16;" :: "r"(dst), "l"(src));
}
#define CP_COMMIT() asm volatile("cp.async.commit_group;" ::: "memory")
#define CP_WAIT(n)  asm volatile("cp.async.wait_group %0;" :: "n"(n) : "memory")

__device__ __forceinline__ uint32_t lds32(uint32_t a) {
    uint32_t v;
    asm volatile("ld.shared.b32 %0, [%1];" : "=r"(v) : "r"(a));
    return v;
}
__device__ __forceinline__ void mma8(float* c, const uint4& a, const uint2& b) {
    asm volatile(
        "mma.sync.aligned.m16n8k8.row.col.f32.tf32.tf32.f32 "
        "{%0,%1,%2,%3}, {%4,%5,%6,%7}, {%8,%9}, {%0,%1,%2,%3};\n"
        : "+f"(c[0]), "+f"(c[1]), "+f"(c[2]), "+f"(c[3])
        : "r"(a.x), "r"(a.y), "r"(a.z), "r"(a.w), "r"(b.x), "r"(b.y));
}

// rna tf32 round + compensation for weight-truncation bias (×(1+2^-11·ln2))
__device__ __forceinline__ float rtf_comp(float x) {
    float v = x * 1.000338f;
    uint32_t u = (__float_as_uint(v) + 0x1000u) & 0xffffe000u;
    return __uint_as_float(u);
}
__device__ __forceinline__ float silu_f(float g) { return g / (1.f + __expf(-g)); }

// SW128 swizzled offset of 16B chunk c (0..7) in row r (128B rows)
__device__ __forceinline__ uint32_t sw_chunk(int r, int c) {
    return (uint32_t)(r * 128 + ((c * 16) ^ ((r & 7) << 4)));
}

// ---------------- router + pre-rounding ----------------
__global__ void zero_counts_kernel() {
    if (threadIdx.x < NEXP) g_count[threadIdx.x] = 0;
}
__global__ __launch_bounds__(256) void round_x_kernel(const float* __restrict__ x) {
    int i = blockIdx.x * 256 + threadIdx.x;
    if (i < T_TOK * HDIM) g_xr[i] = rtf_comp(x[i]);
}
__global__ __launch_bounds__(128) void router_kernel(const float* __restrict__ x,
                                                     const float* __restrict__ gw) {
    const int t = blockIdx.x;
    const int tid = threadIdx.x;
    const int e = tid & 15;
    const int lane = tid >> 4;
    const float* xr = x + (size_t)t * HDIM;
    const float* wr = gw + (size_t)e * HDIM;
    float p = 0.f;
    for (int h = lane; h < HDIM; h += 8) p += xr[h] * wr[h];
    __shared__ float red[16][8];
    red[e][lane] = p;
    __syncthreads();
    if (tid < 16) {
        float s = 0.f;
        #pragma unroll
        for (int j = 0; j < 8; j++) s += red[tid][j];
        red[tid][0] = s;
    }
    __syncthreads();
    if (tid == 0) {
        float lg[16], pr[16];
        float mx = -1e30f;
        #pragma unroll
        for (int i = 0; i < 16; i++) { lg[i] = red[i][0]; mx = fmaxf(mx, lg[i]); }
        float sum = 0.f;
        #pragma unroll
        for (int i = 0; i < 16; i++) { pr[i] = expf(lg[i] - mx); sum += pr[i]; }
        #pragma unroll
        for (int i = 0; i < 16; i++) pr[i] /= sum;
        int used = 0;
        int idx[TOPK]; float wv[TOPK]; float wsum = 0.f;
        #pragma unroll
        for (int k = 0; k < TOPK; k++) {
            float best = -1.f; int bi = 0;
            #pragma unroll
            for (int i = 0; i < 16; i++)
                if (!((used >> i) & 1) && pr[i] > best) { best = pr[i]; bi = i; }
            used |= (1 << bi);
            idx[k] = bi; wv[k] = best; wsum += best;
        }
        #pragma unroll
        for (int k = 0; k < TOPK; k++) {
            g_topw[t * TOPK + k] = wv[k] / wsum;
            int slot = atomicAdd(&g_count[idx[k]], 1);
            g_list[idx[k] * T_TOK + slot] = t * TOPK + k;
        }
    }
}

// =====================================================================
// Generic 128x128x32 HMMA-tf32 GEMM: C = A x B^T
// MODE 0: routed GU  (A=g_xr gathered, B=wgu[e],  C=g_gu[e],   K=2048, cnt)
// MODE 1: routed DN  (A=g_act_r[e],    B=wdown[e],C=g_ds scat, K=1408, cnt)
// MODE 2: shared GU  (A=g_xr,          B=sgu,     C=g_gus,     K=2048)
// MODE 3: shared DN  (A=g_act_s,       B=sdown,   C=out comb,  K=2816)
// =====================================================================
template<int MODE>
__global__ void __launch_bounds__(NTHR) gemm_k(const float* __restrict__ Bext,
                                               float* __restrict__ Cext) {
    constexpr int KD  = (MODE == 1) ? IDIM : (MODE == 3) ? SIDIM : HDIM;
    constexpr int KT  = KD / BK;
    constexpr bool CNT = (MODE <= 1);
    constexpr bool GAT = (MODE == 0);

    extern __shared__ char smx[];
    const int tid = threadIdx.x;
    const int e = blockIdx.z;
    const int cnt = CNT ? g_count[e] : T_TOK;
    const int m0 = blockIdx.x * BM;
    if (m0 >= cnt) return;
    const int n0 = blockIdx.y * BN;

    const uint32_t sb = smem_u32(smx);
    int* rowsm = (int*)(smx + 65536);

    if (GAT || MODE == 1) {
        if (tid < 128) {
            int r = m0 + tid;
            if (r >= cnt) r = cnt - 1;
            rowsm[tid] = g_list[e * T_TOK + r];
        }
        __syncthreads();
    }

    // operand bases
    const float* A;
    long lda;
    if (MODE == 0 || MODE == 2) { A = g_xr; lda = HDIM; }
    else if (MODE == 1) { A = g_act_r + (size_t)e * T_TOK * IDIM; lda = IDIM; }
    else { A = g_act_s; lda = SIDIM; }
    const float* B;
    if (MODE == 0)      B = Bext + (size_t)e * GU2 * HDIM + (size_t)n0 * HDIM;
    else if (MODE == 1) B = Bext + (size_t)e * HDIM * IDIM + (size_t)n0 * IDIM;
    else                B = Bext + (size_t)n0 * KD;

    // staging descriptors (4 A-chunks + 4 B-chunks per thread)
    const float* aSrc[4]; const float* bSrc[4]; uint32_t cOff[4];
    #pragma unroll
    for (int i = 0; i < 4; i++) {
        int ch = tid + i * 256, r = ch >> 3, c = ch & 7;
        int ar;
        if (GAT) ar = rowsm[r] >> 2;
        else { ar = m0 + r; if (CNT && ar >= cnt) ar = cnt - 1; }
        aSrc[i] = A + (size_t)ar * lda + c * 4;
        bSrc[i] = B + (size_t)r * KD + c * 4;
        cOff[i] = sw_chunk(r, c);
    }
    const uint32_t saB[2] = {sb, sb + 16384};
    const uint32_t sbB[2] = {sb + 32768, sb + 49152};

    // per-lane fragment address components
    const int lane = tid & 31, wid = tid >> 5, wm = wid & 3, wn = wid >> 2;
    const int g = lane >> 2, t = lane & 3;
    uint32_t arb[4], axr[4];
    #pragma unroll
    for (int mi = 0; mi < 2; mi++) {
        int r0 = wm * 32 + mi * 16 + g;
        arb[mi * 2]     = r0 * 128;       axr[mi * 2]     = (r0 & 7) << 4;
        arb[mi * 2 + 1] = (r0 + 8) * 128; axr[mi * 2 + 1] = ((r0 + 8) & 7) << 4;
    }
    uint32_t brb[8], bxr[8];
    #pragma unroll
    for (int ni = 0; ni < 8; ni++) {
        int n = wn * 64 + ni * 8 + g;
        brb[ni] = n * 128; bxr[ni] = (n & 7) << 4;
    }

    float acc[16][4];
    #pragma unroll
    for (int i = 0; i < 16; i++)
        #pragma unroll
        for (int j = 0; j < 4; j++) acc[i][j] = 0.f;

    // prologue stage kt=0 -> buf0
    #pragma unroll
    for (int i = 0; i < 4; i++) cpa16(saB[0] + cOff[i], aSrc[i]);
    #pragma unroll
    for (int i = 0; i < 4; i++) cpa16(sbB[0] + cOff[i], bSrc[i]);
    CP_COMMIT();

    for (int kt = 0; kt < KT; kt++) {
        const int cur = kt & 1;
        if (kt + 1 < KT) {
            const int nb = cur ^ 1;
            const size_t ko = (size_t)(kt + 1) * BK;
            #pragma unroll
            for (int i = 0; i < 4; i++) cpa16(saB[nb] + cOff[i], aSrc[i] + ko);
            #pragma unroll
            for (int i = 0; i < 4; i++) cpa16(sbB[nb] + cOff[i], bSrc[i] + ko);
            CP_COMMIT();
            CP_WAIT(1);
        } else {
            CP_WAIT(0);
        }
        __syncthreads();
        const uint32_t sa = saB[cur], sbb = sbB[cur];
        #pragma unroll
        for (int ks = 0; ks < 4; ks++) {
            const uint32_t k4a = ks * 32 + t * 4, k4b = k4a + 16;
            uint4 af[2];
            #pragma unroll
            for (int mi = 0; mi < 2; mi++) {
                af[mi].x = lds32(sa + arb[mi * 2]     + (k4a ^ axr[mi * 2]));
                af[mi].y = lds32(sa + arb[mi * 2 + 1] + (k4a ^ axr[mi * 2 + 1]));
                af[mi].z = lds32(sa + arb[mi * 2]     + (k4b ^ axr[mi * 2]));
                af[mi].w = lds32(sa + arb[mi * 2 + 1] + (k4b ^ axr[mi * 2 + 1]));
            }
            #pragma unroll
            for (int ni = 0; ni < 8; ni++) {
                uint2 bf;
                bf.x = lds32(sbb + brb[ni] + (k4a ^ bxr[ni]));
                bf.y = lds32(sbb + brb[ni] + (k4b ^ bxr[ni]));
                mma8(acc[0 * 8 + ni], af[0], bf);
                mma8(acc[1 * 8 + ni], af[1], bf);
            }
        }
        __syncthreads();
    }

    // epilogue
    #pragma unroll
    for (int mi = 0; mi < 2; mi++) {
        #pragma unroll
        for (int half = 0; half < 2; half++) {
            const int rr = wm * 32 + mi * 16 + g + half * 8;
            const int gr = m0 + rr;
            if (CNT && gr >= cnt) continue;
            const int colb = n0 + wn * 64 + t * 2;
            if (MODE == 0) {
                float* cp = g_gu + ((size_t)e * T_TOK + gr) * GU2 + colb;
                #pragma unroll
                for (int ni = 0; ni < 8; ni++)
                    *(float2*)(cp + ni * 8) = make_float2(acc[mi * 8 + ni][half * 2],
                                                          acc[mi * 8 + ni][half * 2 + 1]);
            } else if (MODE == 1) {
                const int a = rowsm[rr];
                const float w = g_topw[a];
                float* cp = g_ds + (size_t)a * HDIM + colb;
                #pragma unroll
                for (int ni = 0; ni < 8; ni++)
                    *(float2*)(cp + ni * 8) = make_float2(acc[mi * 8 + ni][half * 2] * w,
                                                          acc[mi * 8 + ni][half * 2 + 1] * w);
            } else if (MODE == 2) {
                float* cp = g_gus + (size_t)gr * SGU2 + colb;
                #pragma unroll
                for (int ni = 0; ni < 8; ni++)
                    *(float2*)(cp + ni * 8) = make_float2(acc[mi * 8 + ni][half * 2],
                                                          acc[mi * 8 + ni][half * 2 + 1]);
            } else {
                float* cp = Cext + (size_t)gr * HDIM + colb;
                const float* ds = g_ds + (size_t)gr * TOPK * HDIM + colb;
                #pragma unroll
                for (int ni = 0; ni < 8; ni++) {
                    float s0 = acc[mi * 8 + ni][half * 2];
                    float s1 = acc[mi * 8 + ni][half * 2 + 1];
                    #pragma unroll
                    for (int k = 0; k < TOPK; k++) {
                        float2 d = *(const float2*)(ds + (size_t)k * HDIM + ni * 8);
                        s0 += d.x; s1 += d.y;
                    }
                    *(float2*)(cp + ni * 8) = make_float2(s0, s1);
                }
            }
        }
    }
}

// ---------------- activation elementwise kernels ----------------
__global__ __launch_bounds__(128) void act_routed_kernel() {
    const int e = blockIdx.z;
    const int r = blockIdx.y;
    if (r >= g_count[e]) return;
    const int i = blockIdx.x * 128 + threadIdx.x;   // 0..1407
    const float* row = g_gu + ((size_t)e * T_TOK + r) * GU2;
    float gv = row[i], uv = row[i + IDIM];
    g_act_r[((size_t)e * T_TOK + r) * IDIM + i] = rtf_comp(silu_f(gv) * uv);
}
__global__ __launch_bounds__(128) void act_shared_kernel() {
    const int r = blockIdx.y;
    const int i = blockIdx.x * 128 + threadIdx.x;   // 0..2815
    const float* row = g_gus + (size_t)r * SGU2;
    float gv = row[i], uv = row[i + SIDIM];
    g_act_s[(size_t)r * SIDIM + i] = rtf_comp(silu_f(gv) * uv);
}

// ---------------- launch ----------------
#define SMEMT (65536 + 1024)

extern "C" void kernel_launch(void* const* d_in, const int* in_sizes, int n_in,
                              void* d_out, int out_size) {
    const float* x     = (const float*)d_in[0];
    const float* gw    = (const float*)d_in[1];
    const float* wgu   = (const float*)d_in[2];
    const float* wdown = (const float*)d_in[3];
    const float* sgu   = (const float*)d_in[4];
    const float* sdown = (const float*)d_in[5];
    float* out = (float*)d_out;

    cudaFuncSetAttribute(gemm_k<0>, cudaFuncAttributeMaxDynamicSharedMemorySize, SMEMT);
    cudaFuncSetAttribute(gemm_k<1>, cudaFuncAttributeMaxDynamicSharedMemorySize, SMEMT);
    cudaFuncSetAttribute(gemm_k<2>, cudaFuncAttributeMaxDynamicSharedMemorySize, SMEMT);
    cudaFuncSetAttribute(gemm_k<3>, cudaFuncAttributeMaxDynamicSharedMemorySize, SMEMT);

    zero_counts_kernel<<<1, 32>>>();
    router_kernel<<<T_TOK, 128>>>(x, gw);
    round_x_kernel<<<(T_TOK * HDIM + 255) / 256, 256>>>(x);

    // routed gate/up: per-expert gather GEMM
    gemm_k<0><<<dim3(T_TOK / BM, GU2 / BN, NEXP), NTHR, SMEMT>>>(wgu, nullptr);
    // shared gate/up
    gemm_k<2><<<dim3(T_TOK / BM, SGU2 / BN, 1), NTHR, SMEMT>>>(sgu, nullptr);
    // activations
    act_routed_kernel<<<dim3(IDIM / 128, T_TOK, NEXP), 128>>>();
    act_shared_kernel<<<dim3(SIDIM / 128, T_TOK, 1), 128>>>();
    // routed down (scatter + scale)
    gemm_k<1><<<dim3(T_TOK / BM, HDIM / BN, NEXP), NTHR, SMEMT>>>(wdown, nullptr);
    // shared down + combine
    gemm_k<3><<<dim3(T_TOK / BM, HDIM / BN, 1), NTHR, SMEMT>>>(sdown, out);
}